// round 13
// baseline (speedup 1.0000x reference)
#include <cuda_runtime.h>

#define NB 32
#define NS 1024
#define NV 8

typedef unsigned long long ull;

// per-warp smem layout (floats), float4-aligned
//   0   EMB(32) | 32 LN1G(8) | 40 LN1B(8) | 48 WQKV(96) | 144 WO(32)
// 176 LN2G(8) | 184 LN2B(8) | 192 W1(128) | 320 B1(32) | 352 B2(8)
// 360 OUTW(32) | 392 W2T(128, transposed [l][fl][e]) | 520 SKV(2*64) | 648 SLOG(64)
#define O_EMB   0
#define O_LN1G  32
#define O_LN1B  40
#define O_WQKV  48
#define O_WO    144
#define O_LN2G  176
#define O_LN2B  184
#define O_W1    192
#define O_B1    320
#define O_B2    352
#define O_OUTW  360
#define O_W2T   392
#define O_SKV   520
#define O_SLOG  648
#define WSTRIDE 712

__device__ __forceinline__ float ex2(float x) {
    float y;
    asm("ex2.approx.ftz.f32 %0, %1;" : "=f"(y) : "f"(x));
    return y;
}
__device__ __forceinline__ float4 ld4(const float* p) { return *(const float4*)p; }

// ---------------------------------------------------------------------------
// ONE kernel, one block per batch (256 threads = 8 warps), ZERO block barriers.
// Every warp is fully autonomous (only __syncwarp):
//   - loads all 1024 batch tokens itself (L1-hot after warp 0), builds the full
//     histogram warp-locally (byte-packed -> 16-bit fields, 10 shfl.b64),
//   - stages a private copy of all weights into its own smem region,
//   - runs the 2-layer network for the 8 distinct token states (vocab=8, no
//     positional encoding => equal ids share state; attention = histogram-
//     weighted 8-term sum) with lanes = 8 states x 4 roles: QKV/attention
//     replicated per role, FFN split 4 ways (4 erff/lane, shfl_xor reduce),
//     K/V exchanged through warp-private smem (+__syncwarp),
//   - computes 2 logits/lane, scatters its own 128-token chunk (STG.128).
// ---------------------------------------------------------------------------
__global__ void __launch_bounds__(256) fused_kernel(
    const int*   __restrict__ tok,
    const float* __restrict__ emb,
    const float* __restrict__ ln1_g, const float* __restrict__ ln1_b,
    const float* __restrict__ wqkv,  const float* __restrict__ wo,
    const float* __restrict__ ln2_g, const float* __restrict__ ln2_b,
    const float* __restrict__ w1,    const float* __restrict__ b1,
    const float* __restrict__ w2,    const float* __restrict__ b2,
    const float* __restrict__ out_w,
    float* __restrict__ out)
{
    __shared__ __align__(16) float smem[8 * WSTRIDE];

    const int b    = blockIdx.x;
    const int t    = threadIdx.x;
    const int warp = t >> 5;
    const int lane = t & 31;
    float* sp = smem + warp * WSTRIDE;             // this warp's private region

    // ---- tokens: whole batch, 8 int4 per lane (chunk #warp is ours) ----
    const int4* tp = (const int4*)(tok + b * NS);
    int4 tk[8];
    #pragma unroll
    for (int k = 0; k < 8; k++) tk[k] = tp[lane + 32 * k];
    int4 my;                                       // tk[warp] without dynamic idx
    #pragma unroll
    for (int k = 0; k < 8; k++) if (k == warp) my = tk[k];

    // ---- private weight staging (98 float4 + 128 transposed-w2 scalars) ----
    #pragma unroll
    for (int k = 0; k < 4; k++) {
        int idx = lane + 32 * k;
        if (idx < 98) {
            const float4* src;
            if      (idx < 8)  src = (const float4*)emb   + idx;
            else if (idx < 10) src = (const float4*)ln1_g + (idx - 8);
            else if (idx < 12) src = (const float4*)ln1_b + (idx - 10);
            else if (idx < 36) src = (const float4*)wqkv  + (idx - 12);
            else if (idx < 44) src = (const float4*)wo    + (idx - 36);
            else if (idx < 46) src = (const float4*)ln2_g + (idx - 44);
            else if (idx < 48) src = (const float4*)ln2_b + (idx - 46);
            else if (idx < 80) src = (const float4*)w1    + (idx - 48);
            else if (idx < 88) src = (const float4*)b1    + (idx - 80);
            else if (idx < 90) src = (const float4*)b2    + (idx - 88);
            else               src = (const float4*)out_w + (idx - 90);
            ((float4*)sp)[idx] = *src;
        }
        int i  = lane + 32 * k;                    // w2t: [l][fl][e]
        int l  = i >> 6, fl = (i >> 2) & 15, e = i & 3;
        sp[O_W2T + i] = w2[l * 64 + e * 16 + fl];
    }

    // ---- warp-local full histogram (byte fields -> 16-bit fields) ----
    ull c = 0;
    #pragma unroll
    for (int k = 0; k < 8; k++) {
        c += (1ull << (tk[k].x * 8)) + (1ull << (tk[k].y * 8))
           + (1ull << (tk[k].z * 8)) + (1ull << (tk[k].w * 8));
    }                                              // per-lane bins <= 32: no carry
    ull lo =  c       & 0x00FF00FF00FF00FFull;     // ids 0,2,4,6
    ull hi = (c >> 8) & 0x00FF00FF00FF00FFull;     // ids 1,3,5,7
    #pragma unroll
    for (int o = 16; o; o >>= 1) {
        lo += __shfl_xor_sync(0xffffffffu, lo, o);
        hi += __shfl_xor_sync(0xffffffffu, hi, o); // sums <= 1024: 16-bit safe
    }
    float cw[8];
    cw[0] = (float)( lo        & 0xFFFF); cw[1] = (float)( hi        & 0xFFFF);
    cw[2] = (float)((lo >> 16) & 0xFFFF); cw[3] = (float)((hi >> 16) & 0xFFFF);
    cw[4] = (float)((lo >> 32) & 0xFFFF); cw[5] = (float)((hi >> 32) & 0xFFFF);
    cw[6] = (float)((lo >> 48) & 0xFFFF); cw[7] = (float)( hi >> 48);

    __syncwarp();                                  // weights visible

    // ---- network: lanes = 8 states x 4 roles ----
    const int s = lane >> 2, r = lane & 3;
    float4 ev = ld4(sp + O_EMB + s * 4);
    float x0 = ev.x, x1 = ev.y, x2 = ev.z, x3 = ev.w;
    const float SC = 0.70710678118654752f * 1.4426950408889634f;

    #pragma unroll
    for (int l = 0; l < 2; l++) {
        // LN1
        float4 g1 = ld4(sp + O_LN1G + l*4), b1v = ld4(sp + O_LN1B + l*4);
        float mu = 0.25f*(x0+x1+x2+x3);
        float d0 = x0-mu, d1 = x1-mu, d2 = x2-mu, d3 = x3-mu;
        float rr = rsqrtf(0.25f*(d0*d0+d1*d1+d2*d2+d3*d3) + 1e-5f);
        float h0 = d0*rr*g1.x+b1v.x, h1 = d1*rr*g1.y+b1v.y;
        float h2 = d2*rr*g1.z+b1v.z, h3 = d3*rr*g1.w+b1v.w;

        // QKV: 12 vector rows (replicated per role)
        float qk[12];
        #pragma unroll
        for (int f = 0; f < 12; f++) {
            float4 wr = ld4(sp + O_WQKV + l*48 + f*4);
            qk[f] = fmaf(h0, wr.x, fmaf(h1, wr.y, fmaf(h2, wr.z, h3 * wr.w)));
        }

        // publish this state's K and V (role 0), warp-private smem
        if (r == 0) {
            float4* dst = (float4*)(sp + O_SKV + (l*8 + s) * 8);
            dst[0] = make_float4(qk[4], qk[5], qk[6],  qk[7]);
            dst[1] = make_float4(qk[8], qk[9], qk[10], qk[11]);
        }
        __syncwarp();

        float q00 = qk[0]*SC, q01 = qk[1]*SC;      // head0
        float q10 = qk[2]*SC, q11 = qk[3]*SC;      // head1

        // histogram-weighted softmax over the 8 states
        float den0 = 0.f, a00 = 0.f, a01 = 0.f;
        float den1 = 0.f, a10 = 0.f, a11 = 0.f;
        #pragma unroll
        for (int j = 0; j < 8; j++) {
            const float4* kv = (const float4*)(sp + O_SKV + (l*8 + j) * 8);
            float4 k4 = kv[0];
            float4 v4 = kv[1];
            float wa = cw[j] * ex2(fmaf(q00, k4.x, q01*k4.y));
            float wb = cw[j] * ex2(fmaf(q10, k4.z, q11*k4.w));
            den0 += wa; a00 = fmaf(wa, v4.x, a00); a01 = fmaf(wa, v4.y, a01);
            den1 += wb; a10 = fmaf(wb, v4.z, a10); a11 = fmaf(wb, v4.w, a11);
        }
        float inv0 = 1.0f/den0, inv1 = 1.0f/den1;
        float o0 = a00*inv0, o1 = a01*inv0;
        float o2 = a10*inv1, o3 = a11*inv1;

        // Wo projection + residual
        float4 wo0 = ld4(sp + O_WO + l*16 + 0);
        float4 wo1 = ld4(sp + O_WO + l*16 + 4);
        float4 wo2 = ld4(sp + O_WO + l*16 + 8);
        float4 wo3 = ld4(sp + O_WO + l*16 + 12);
        float y0 = x0 + o0*wo0.x + o1*wo0.y + o2*wo0.z + o3*wo0.w;
        float y1 = x1 + o0*wo1.x + o1*wo1.y + o2*wo1.z + o3*wo1.w;
        float y2 = x2 + o0*wo2.x + o1*wo2.y + o2*wo2.z + o3*wo2.w;
        float y3 = x3 + o0*wo3.x + o1*wo3.y + o2*wo3.z + o3*wo3.w;

        // LN2
        float4 g2 = ld4(sp + O_LN2G + l*4), b2v = ld4(sp + O_LN2B + l*4);
        mu = 0.25f*(y0+y1+y2+y3);
        d0 = y0-mu; d1 = y1-mu; d2 = y2-mu; d3 = y3-mu;
        rr = rsqrtf(0.25f*(d0*d0+d1*d1+d2*d2+d3*d3) + 1e-5f);
        h0 = d0*rr*g2.x+b2v.x; h1 = d1*rr*g2.y+b2v.y;
        h2 = d2*rr*g2.z+b2v.z; h3 = d3*rr*g2.w+b2v.w;

        // FFN: role r owns hidden units r*4..r*4+3 (4 erff per lane)
        float p0 = 0.f, p1 = 0.f, p2 = 0.f, p3 = 0.f;
        #pragma unroll
        for (int j = 0; j < 4; j++) {
            int fl = r * 4 + j;
            float4 w1r = ld4(sp + O_W1 + l*64 + fl*4);
            float  bb  = sp[O_B1 + l*16 + fl];
            float ss = fmaf(h0, w1r.x, fmaf(h1, w1r.y, fmaf(h2, w1r.z, fmaf(h3, w1r.w, bb))));
            float u  = 0.5f * ss * (1.0f + erff(ss * 0.70710678118654752f)); // exact gelu
            float4 w2r = ld4(sp + O_W2T + l*64 + fl*4);
            p0 = fmaf(u, w2r.x, p0); p1 = fmaf(u, w2r.y, p1);
            p2 = fmaf(u, w2r.z, p2); p3 = fmaf(u, w2r.w, p3);
        }
        #pragma unroll
        for (int m = 1; m <= 2; m <<= 1) {         // reduce over the 4 roles
            p0 += __shfl_xor_sync(0xffffffffu, p0, m);
            p1 += __shfl_xor_sync(0xffffffffu, p1, m);
            p2 += __shfl_xor_sync(0xffffffffu, p2, m);
            p3 += __shfl_xor_sync(0xffffffffu, p3, m);
        }
        float4 bf2 = ld4(sp + O_B2 + l*4);
        x0 = y0 + bf2.x + p0;
        x1 = y1 + bf2.y + p1;
        x2 = y2 + bf2.z + p2;
        x3 = y3 + bf2.w + p3;
    }

    // ---- logits: role r computes logits 2r, 2r+1 of state s ----
    {
        float4 owa = ld4(sp + O_OUTW + (2*r)     * 4);
        float4 owb = ld4(sp + O_OUTW + (2*r + 1) * 4);
        float la = fmaf(x0, owa.x, fmaf(x1, owa.y, fmaf(x2, owa.z, x3 * owa.w)));
        float lb = fmaf(x0, owb.x, fmaf(x1, owb.y, fmaf(x2, owb.z, x3 * owb.w)));
        *(float2*)(sp + O_SLOG + s * 8 + 2 * r) = make_float2(la, lb);
    }
    __syncwarp();

    // ---- scatter: this warp's 128-token chunk (4 tokens/thread, 128B) ----
    float4* op = (float4*)(out + ((size_t)b * NS + 4 * t) * NV);
    const float4* l0 = (const float4*)(sp + O_SLOG + my.x * NV);
    const float4* l1 = (const float4*)(sp + O_SLOG + my.y * NV);
    const float4* l2 = (const float4*)(sp + O_SLOG + my.z * NV);
    const float4* l3 = (const float4*)(sp + O_SLOG + my.w * NV);
    op[0] = l0[0]; op[1] = l0[1];
    op[2] = l1[0]; op[3] = l1[1];
    op[4] = l2[0]; op[5] = l2[1];
    op[6] = l3[0]; op[7] = l3[1];
}

// ---------------------------------------------------------------------------
extern "C" void kernel_launch(void* const* d_in, const int* in_sizes, int n_in,
                              void* d_out, int out_size)
{
    const int*   tok   = (const int*)  d_in[0];
    const float* emb   = (const float*)d_in[1];
    const float* ln1_g = (const float*)d_in[2];
    const float* ln1_b = (const float*)d_in[3];
    const float* wqkv  = (const float*)d_in[4];
    const float* wo    = (const float*)d_in[5];
    const float* ln2_g = (const float*)d_in[6];
    const float* ln2_b = (const float*)d_in[7];
    const float* w1    = (const float*)d_in[8];
    const float* b1    = (const float*)d_in[9];
    const float* w2    = (const float*)d_in[10];
    const float* b2    = (const float*)d_in[11];
    const float* out_w = (const float*)d_in[12];
    float* out = (float*)d_out;

    fused_kernel<<<NB, 256>>>(tok, emb, ln1_g, ln1_b, wqkv, wo,
                              ln2_g, ln2_b, w1, b1, w2, b2, out_w, out);
}

// round 14
// speedup vs baseline: 1.6119x; 1.6119x over previous
#include <cuda_runtime.h>

#define NB 32
#define NS 1024
#define NV 8

typedef unsigned long long ull;

// smem layout (floats), float4-aligned
//   0 EMB(32) | 32 LN1G(8) | 40 LN1B(8) | 48 WQKV(96) | 144 WO(32)
// 176 LN2G(8) | 184 LN2B(8) | 192 W1(128) | 320 B1(32) | 352 B2(8)
// 360 OUTW(32) | 392 W2T(128: [l][fl][e]) | 520 SKV(128) | 648 SLOG(64)
#define O_EMB   0
#define O_LN1G  32
#define O_LN1B  40
#define O_WQKV  48
#define O_WO    144
#define O_LN2G  176
#define O_LN2B  184
#define O_W1    192
#define O_B1    320
#define O_B2    352
#define O_OUTW  360
#define O_W2T   392
#define O_SKV   520
#define O_SLOG  648
#define S_TOTAL 712

__device__ __forceinline__ float ex2(float x) {
    float y;
    asm("ex2.approx.ftz.f32 %0, %1;" : "=f"(y) : "f"(x));
    return y;
}
__device__ __forceinline__ float4 ld4(const float* p) { return *(const float4*)p; }

// ---------------------------------------------------------------------------
// ONE kernel, one block per batch (256 threads = 8 warps), ONE block barrier.
//   Warp 0 alone: loads all 1024 tokens (8 LDG.128/lane, one DRAM round-trip),
//   stages all weights (+transposed w2), builds the histogram warp-locally,
//   then runs the 2-layer network for the 8 distinct token states (vocab=8,
//   no positional encoding => equal ids share state; attention = histogram-
//   weighted 8-term sum) with lanes = 8 states x 4 roles. Role pairs split
//   the two heads (8 ex2/lane/layer); FFN split 4 ways (4 erff/lane);
//   K/V exchanged via smem + __syncwarp only. Logits -> smem.
//   Warps 1-7: load their token chunk, wait at the single __syncthreads.
//   All warps: scatter their own 128-token chunk (4 tokens -> 128B STG.128).
// ---------------------------------------------------------------------------
__global__ void __launch_bounds__(256) fused_kernel(
    const int*   __restrict__ tok,
    const float* __restrict__ emb,
    const float* __restrict__ ln1_g, const float* __restrict__ ln1_b,
    const float* __restrict__ wqkv,  const float* __restrict__ wo,
    const float* __restrict__ ln2_g, const float* __restrict__ ln2_b,
    const float* __restrict__ w1,    const float* __restrict__ b1,
    const float* __restrict__ w2,    const float* __restrict__ b2,
    const float* __restrict__ out_w,
    float* __restrict__ out)
{
    __shared__ __align__(16) float sw[S_TOTAL];

    const int b    = blockIdx.x;
    const int t    = threadIdx.x;
    const int warp = t >> 5;
    const int lane = t & 31;

    const int4* tp = (const int4*)(tok + b * NS);
    int4 my;                                       // this thread's 4 scatter tokens

    if (warp == 0) {
        // ---- tokens: all 8 chunks (one round-trip, also feeds histogram) ----
        int4 tk[8];
        #pragma unroll
        for (int k = 0; k < 8; k++) tk[k] = tp[lane + 32 * k];
        my = tk[0];

        // ---- weight staging: 98 float4 + 128 transposed-w2 scalars ----
        #pragma unroll
        for (int k = 0; k < 4; k++) {
            int idx = lane + 32 * k;
            if (idx < 98) {
                const float4* src;
                if      (idx < 8)  src = (const float4*)emb   + idx;
                else if (idx < 10) src = (const float4*)ln1_g + (idx - 8);
                else if (idx < 12) src = (const float4*)ln1_b + (idx - 10);
                else if (idx < 36) src = (const float4*)wqkv  + (idx - 12);
                else if (idx < 44) src = (const float4*)wo    + (idx - 36);
                else if (idx < 46) src = (const float4*)ln2_g + (idx - 44);
                else if (idx < 48) src = (const float4*)ln2_b + (idx - 46);
                else if (idx < 80) src = (const float4*)w1    + (idx - 48);
                else if (idx < 88) src = (const float4*)b1    + (idx - 80);
                else if (idx < 90) src = (const float4*)b2    + (idx - 88);
                else               src = (const float4*)out_w + (idx - 90);
                ((float4*)sw)[idx] = *src;
            }
            int i  = lane + 32 * k;                // w2t: [l][fl][e]
            int l  = i >> 6, fl = (i >> 2) & 15, e = i & 3;
            sw[O_W2T + i] = w2[l * 64 + e * 16 + fl];
        }

        // ---- warp-local histogram (byte fields -> 16-bit fields) ----
        ull c = 0;
        #pragma unroll
        for (int k = 0; k < 8; k++) {
            c += (1ull << (tk[k].x * 8)) + (1ull << (tk[k].y * 8))
               + (1ull << (tk[k].z * 8)) + (1ull << (tk[k].w * 8));
        }                                          // per-lane bins <= 32: no carry
        ull lo =  c       & 0x00FF00FF00FF00FFull; // ids 0,2,4,6
        ull hi = (c >> 8) & 0x00FF00FF00FF00FFull; // ids 1,3,5,7
        #pragma unroll
        for (int o = 16; o; o >>= 1) {
            lo += __shfl_xor_sync(0xffffffffu, lo, o);
            hi += __shfl_xor_sync(0xffffffffu, hi, o); // sums <= 1024: 16-bit ok
        }
        float cw[8];
        cw[0] = (float)( lo        & 0xFFFF); cw[1] = (float)( hi        & 0xFFFF);
        cw[2] = (float)((lo >> 16) & 0xFFFF); cw[3] = (float)((hi >> 16) & 0xFFFF);
        cw[4] = (float)((lo >> 32) & 0xFFFF); cw[5] = (float)((hi >> 32) & 0xFFFF);
        cw[6] = (float)((lo >> 48) & 0xFFFF); cw[7] = (float)( hi >> 48);

        __syncwarp();                              // staged weights visible

        // ---- network: lanes = 8 states x 4 roles; roles {0,1}=head0 {2,3}=head1
        const int s  = lane >> 2, r = lane & 3;
        const int hr = r >> 1;                     // this lane's head
        float4 ev = ld4(sw + O_EMB + s * 4);
        float x0 = ev.x, x1 = ev.y, x2 = ev.z, x3 = ev.w;
        const float SC = 0.70710678118654752f * 1.4426950408889634f;

        #pragma unroll
        for (int l = 0; l < 2; l++) {
            // LN1
            float4 g1 = ld4(sw + O_LN1G + l*4), b1v = ld4(sw + O_LN1B + l*4);
            float mu = 0.25f*(x0+x1+x2+x3);
            float d0 = x0-mu, d1 = x1-mu, d2 = x2-mu, d3 = x3-mu;
            float rr = rsqrtf(0.25f*(d0*d0+d1*d1+d2*d2+d3*d3) + 1e-5f);
            float h0 = d0*rr*g1.x+b1v.x, h1 = d1*rr*g1.y+b1v.y;
            float h2 = d2*rr*g1.z+b1v.z, h3 = d3*rr*g1.w+b1v.w;

            // K,V: 8 dots (all lanes); q: 2 dots for own head only
            float kv[8];
            #pragma unroll
            for (int f = 0; f < 8; f++) {
                float4 wr = ld4(sw + O_WQKV + l*48 + (4+f)*4);
                kv[f] = fmaf(h0, wr.x, fmaf(h1, wr.y, fmaf(h2, wr.z, h3 * wr.w)));
            }
            float qa, qb;
            {
                float4 wa = ld4(sw + O_WQKV + l*48 + (2*hr)     * 4);
                float4 wb = ld4(sw + O_WQKV + l*48 + (2*hr + 1) * 4);
                qa = fmaf(h0, wa.x, fmaf(h1, wa.y, fmaf(h2, wa.z, h3 * wa.w))) * SC;
                qb = fmaf(h0, wb.x, fmaf(h1, wb.y, fmaf(h2, wb.z, h3 * wb.w))) * SC;
            }

            // publish this state's K and V (role 0)
            if (r == 0) {
                float4* dst = (float4*)(sw + O_SKV + (l*8 + s) * 8);
                dst[0] = make_float4(kv[0], kv[1], kv[2], kv[3]);
                dst[1] = make_float4(kv[4], kv[5], kv[6], kv[7]);
            }
            __syncwarp();

            // histogram-weighted softmax over 8 states, own head only (8 ex2)
            float den = 0.f, aa = 0.f, ab = 0.f;
            #pragma unroll
            for (int j = 0; j < 8; j++) {
                const float4* kvp = (const float4*)(sw + O_SKV + (l*8 + j) * 8);
                float4 k4 = kvp[0];
                float4 v4 = kvp[1];
                float ka = hr ? k4.z : k4.x, kb = hr ? k4.w : k4.y;
                float va = hr ? v4.z : v4.x, vb = hr ? v4.w : v4.y;
                float w  = cw[j] * ex2(fmaf(qa, ka, qb * kb));
                den += w; aa = fmaf(w, va, aa); ab = fmaf(w, vb, ab);
            }
            float inv = 1.0f / den;
            float oa = aa * inv, ob = ab * inv;

            // recombine heads: partner role is lane^2 (other head, same state)
            float oax = __shfl_xor_sync(0xffffffffu, oa, 2);
            float obx = __shfl_xor_sync(0xffffffffu, ob, 2);
            float o0 = hr ? oax : oa, o1 = hr ? obx : ob;
            float o2 = hr ? oa : oax, o3 = hr ? ob : obx;

            // Wo projection + residual
            float4 wo0 = ld4(sw + O_WO + l*16 + 0);
            float4 wo1 = ld4(sw + O_WO + l*16 + 4);
            float4 wo2 = ld4(sw + O_WO + l*16 + 8);
            float4 wo3 = ld4(sw + O_WO + l*16 + 12);
            float y0 = x0 + o0*wo0.x + o1*wo0.y + o2*wo0.z + o3*wo0.w;
            float y1 = x1 + o0*wo1.x + o1*wo1.y + o2*wo1.z + o3*wo1.w;
            float y2 = x2 + o0*wo2.x + o1*wo2.y + o2*wo2.z + o3*wo2.w;
            float y3 = x3 + o0*wo3.x + o1*wo3.y + o2*wo3.z + o3*wo3.w;

            // LN2
            float4 g2 = ld4(sw + O_LN2G + l*4), b2v = ld4(sw + O_LN2B + l*4);
            mu = 0.25f*(y0+y1+y2+y3);
            d0 = y0-mu; d1 = y1-mu; d2 = y2-mu; d3 = y3-mu;
            rr = rsqrtf(0.25f*(d0*d0+d1*d1+d2*d2+d3*d3) + 1e-5f);
            h0 = d0*rr*g2.x+b2v.x; h1 = d1*rr*g2.y+b2v.y;
            h2 = d2*rr*g2.z+b2v.z; h3 = d3*rr*g2.w+b2v.w;

            // FFN: role r owns hidden units 4r..4r+3 (4 erff/lane)
            float p0 = 0.f, p1 = 0.f, p2 = 0.f, p3 = 0.f;
            #pragma unroll
            for (int j = 0; j < 4; j++) {
                int fl = r * 4 + j;
                float4 w1r = ld4(sw + O_W1 + l*64 + fl*4);
                float  bb  = sw[O_B1 + l*16 + fl];
                float ss = fmaf(h0, w1r.x, fmaf(h1, w1r.y,
                           fmaf(h2, w1r.z, fmaf(h3, w1r.w, bb))));
                float u  = 0.5f * ss * (1.0f + erff(ss * 0.70710678118654752f));
                float4 w2r = ld4(sw + O_W2T + l*64 + fl*4);
                p0 = fmaf(u, w2r.x, p0); p1 = fmaf(u, w2r.y, p1);
                p2 = fmaf(u, w2r.z, p2); p3 = fmaf(u, w2r.w, p3);
            }
            #pragma unroll
            for (int m = 1; m <= 2; m <<= 1) {     // reduce over the 4 roles
                p0 += __shfl_xor_sync(0xffffffffu, p0, m);
                p1 += __shfl_xor_sync(0xffffffffu, p1, m);
                p2 += __shfl_xor_sync(0xffffffffu, p2, m);
                p3 += __shfl_xor_sync(0xffffffffu, p3, m);
            }
            float4 bf2 = ld4(sw + O_B2 + l*4);
            x0 = y0 + bf2.x + p0;
            x1 = y1 + bf2.y + p1;
            x2 = y2 + bf2.z + p2;
            x3 = y3 + bf2.w + p3;
        }

        // logits: role r computes logits 2r, 2r+1 of state s
        float4 owa = ld4(sw + O_OUTW + (2*r)     * 4);
        float4 owb = ld4(sw + O_OUTW + (2*r + 1) * 4);
        float la = fmaf(x0, owa.x, fmaf(x1, owa.y, fmaf(x2, owa.z, x3 * owa.w)));
        float lb = fmaf(x0, owb.x, fmaf(x1, owb.y, fmaf(x2, owb.z, x3 * owb.w)));
        *(float2*)(sw + O_SLOG + s * 8 + 2 * r) = make_float2(la, lb);
    } else {
        my = tp[t];                                // own 4 scatter tokens
    }

    __syncthreads();                               // the ONLY block barrier

    // ---- scatter: 4 contiguous tokens per thread (2x STG.128 each) ----
    float4* op = (float4*)(out + ((size_t)b * NS + 4 * t) * NV);
    const float4* l0 = (const float4*)(sw + O_SLOG + my.x * NV);
    const float4* l1 = (const float4*)(sw + O_SLOG + my.y * NV);
    const float4* l2 = (const float4*)(sw + O_SLOG + my.z * NV);
    const float4* l3 = (const float4*)(sw + O_SLOG + my.w * NV);
    op[0] = l0[0]; op[1] = l0[1];
    op[2] = l1[0]; op[3] = l1[1];
    op[4] = l2[0]; op[5] = l2[1];
    op[6] = l3[0]; op[7] = l3[1];
}

// ---------------------------------------------------------------------------
extern "C" void kernel_launch(void* const* d_in, const int* in_sizes, int n_in,
                              void* d_out, int out_size)
{
    const int*   tok   = (const int*)  d_in[0];
    const float* emb   = (const float*)d_in[1];
    const float* ln1_g = (const float*)d_in[2];
    const float* ln1_b = (const float*)d_in[3];
    const float* wqkv  = (const float*)d_in[4];
    const float* wo    = (const float*)d_in[5];
    const float* ln2_g = (const float*)d_in[6];
    const float* ln2_b = (const float*)d_in[7];
    const float* w1    = (const float*)d_in[8];
    const float* b1    = (const float*)d_in[9];
    const float* w2    = (const float*)d_in[10];
    const float* b2    = (const float*)d_in[11];
    const float* out_w = (const float*)d_in[12];
    float* out = (float*)d_out;

    fused_kernel<<<NB, 256>>>(tok, emb, ln1_g, ln1_b, wqkv, wo,
                              ln2_g, ln2_b, w1, b1, w2, b2, out_w, out);
}

// round 15
// speedup vs baseline: 1.6523x; 1.0251x over previous
#include <cuda_runtime.h>

#define NB 32
#define NS 1024
#define NV 8

typedef unsigned long long ull;

// smem layout (floats), float4-aligned
#define O_EMB   0
#define O_LN1G  32
#define O_LN1B  40
#define O_WQKV  48
#define O_WO    144
#define O_LN2G  176
#define O_LN2B  184
#define O_W1    192
#define O_B1    320
#define O_B2    352
#define O_OUTW  360
#define O_W2T   392
#define O_SKV   520   // [l][state][head][k0,k1,v0,v1] = 2*8*2*4 floats
#define O_SLOG  648
#define S_TOTAL 712

__device__ __forceinline__ float ex2(float x) {
    float y; asm("ex2.approx.ftz.f32 %0, %1;" : "=f"(y) : "f"(x)); return y;
}
__device__ __forceinline__ float rcpa(float x) {
    float y; asm("rcp.approx.ftz.f32 %0, %1;" : "=f"(y) : "f"(x)); return y;
}
__device__ __forceinline__ float rsqa(float x) {
    float y; asm("rsqrt.approx.ftz.f32 %0, %1;" : "=f"(y) : "f"(x)); return y;
}
__device__ __forceinline__ float4 ld4(const float* p) { return *(const float4*)p; }

// Branch-free erf (Abramowitz-Stegun 7.1.26, |abs err| <= 1.5e-7).
// exp(-x^2) underflows to 0 for large |x| (ftz) -> clean saturation, no branch.
__device__ __forceinline__ float erf_bf(float x) {
    float ax = fabsf(x);
    float t  = rcpa(fmaf(0.3275911f, ax, 1.0f));
    float p  = t * fmaf(t, fmaf(t, fmaf(t, fmaf(t, 1.061405429f, -1.453152027f),
                     1.421413741f), -0.284496736f), 0.254829592f);
    float e  = ex2(-1.4426950408889634f * ax * ax);
    return copysignf(fmaf(-p, e, 1.0f), x);
}

// ---------------------------------------------------------------------------
// ONE kernel, one block per batch (256 threads = 8 warps), ONE block barrier.
//   Warp 0 alone: loads all 1024 tokens (8 LDG.128/lane), stages all weights
//   (+transposed w2), builds the histogram warp-locally, then runs the 2-layer
//   network for the 8 distinct token states (vocab=8, no positional encoding
//   => equal ids share state; attention = histogram-weighted 8-term sum) with
//   lanes = 8 states x 4 roles; role pairs split the two heads (8 ex2/lane/
//   layer); FFN split 4 ways (4 branch-free gelu/lane); K/V exchanged via
//   smem + __syncwarp only. Logits -> smem.
//   Warps 1-7: load their token chunk, wait at the single __syncthreads.
//   All warps: scatter their own 128-token chunk (4 tokens -> 128B STG.128).
// ---------------------------------------------------------------------------
__global__ void __launch_bounds__(256) fused_kernel(
    const int*   __restrict__ tok,
    const float* __restrict__ emb,
    const float* __restrict__ ln1_g, const float* __restrict__ ln1_b,
    const float* __restrict__ wqkv,  const float* __restrict__ wo,
    const float* __restrict__ ln2_g, const float* __restrict__ ln2_b,
    const float* __restrict__ w1,    const float* __restrict__ b1,
    const float* __restrict__ w2,    const float* __restrict__ b2,
    const float* __restrict__ out_w,
    float* __restrict__ out)
{
    __shared__ __align__(16) float sw[S_TOTAL];

    const int b    = blockIdx.x;
    const int t    = threadIdx.x;
    const int warp = t >> 5;
    const int lane = t & 31;

    const int4* tp = (const int4*)(tok + b * NS);
    int4 my;                                       // this thread's 4 scatter tokens

    if (warp == 0) {
        // ---- tokens: all 8 chunks (one round-trip, also feeds histogram) ----
        int4 tk[8];
        #pragma unroll
        for (int k = 0; k < 8; k++) tk[k] = tp[lane + 32 * k];
        my = tk[0];

        // ---- weight staging: 98 float4 + 128 transposed-w2 scalars ----
        #pragma unroll
        for (int k = 0; k < 4; k++) {
            int idx = lane + 32 * k;
            if (idx < 98) {
                const float4* src;
                if      (idx < 8)  src = (const float4*)emb   + idx;
                else if (idx < 10) src = (const float4*)ln1_g + (idx - 8);
                else if (idx < 12) src = (const float4*)ln1_b + (idx - 10);
                else if (idx < 36) src = (const float4*)wqkv  + (idx - 12);
                else if (idx < 44) src = (const float4*)wo    + (idx - 36);
                else if (idx < 46) src = (const float4*)ln2_g + (idx - 44);
                else if (idx < 48) src = (const float4*)ln2_b + (idx - 46);
                else if (idx < 80) src = (const float4*)w1    + (idx - 48);
                else if (idx < 88) src = (const float4*)b1    + (idx - 80);
                else if (idx < 90) src = (const float4*)b2    + (idx - 88);
                else               src = (const float4*)out_w + (idx - 90);
                ((float4*)sw)[idx] = *src;
            }
            int i  = lane + 32 * k;                // w2t: [l][fl][e]
            int l  = i >> 6, fl = (i >> 2) & 15, e = i & 3;
            sw[O_W2T + i] = w2[l * 64 + e * 16 + fl];
        }

        // ---- warp-local histogram (byte fields -> 16-bit fields) ----
        ull c = 0;
        #pragma unroll
        for (int k = 0; k < 8; k++) {
            c += (1ull << (tk[k].x * 8)) + (1ull << (tk[k].y * 8))
               + (1ull << (tk[k].z * 8)) + (1ull << (tk[k].w * 8));
        }                                          // per-lane bins <= 32: no carry
        ull lo =  c       & 0x00FF00FF00FF00FFull; // ids 0,2,4,6
        ull hi = (c >> 8) & 0x00FF00FF00FF00FFull; // ids 1,3,5,7
        #pragma unroll
        for (int o = 16; o; o >>= 1) {
            lo += __shfl_xor_sync(0xffffffffu, lo, o);
            hi += __shfl_xor_sync(0xffffffffu, hi, o); // sums <= 1024: 16-bit ok
        }
        float cw[8];
        cw[0] = (float)( lo        & 0xFFFF); cw[1] = (float)( hi        & 0xFFFF);
        cw[2] = (float)((lo >> 16) & 0xFFFF); cw[3] = (float)((hi >> 16) & 0xFFFF);
        cw[4] = (float)((lo >> 32) & 0xFFFF); cw[5] = (float)((hi >> 32) & 0xFFFF);
        cw[6] = (float)((lo >> 48) & 0xFFFF); cw[7] = (float)( hi >> 48);

        __syncwarp();                              // staged weights visible

        // ---- network: lanes = 8 states x 4 roles; roles {0,1}=head0 {2,3}=head1
        const int s  = lane >> 2, r = lane & 3;
        const int hr = r >> 1;                     // this lane's head
        float4 ev = ld4(sw + O_EMB + s * 4);
        float x0 = ev.x, x1 = ev.y, x2 = ev.z, x3 = ev.w;
        const float SC = 0.70710678118654752f * 1.4426950408889634f;

        #pragma unroll
        for (int l = 0; l < 2; l++) {
            // LN1
            float4 g1 = ld4(sw + O_LN1G + l*4), b1v = ld4(sw + O_LN1B + l*4);
            float mu = 0.25f*(x0+x1+x2+x3);
            float d0 = x0-mu, d1 = x1-mu, d2 = x2-mu, d3 = x3-mu;
            float rr = rsqa(fmaf(0.25f, d0*d0+d1*d1+d2*d2+d3*d3, 1e-5f));
            float h0 = d0*rr*g1.x+b1v.x, h1 = d1*rr*g1.y+b1v.y;
            float h2 = d2*rr*g1.z+b1v.z, h3 = d3*rr*g1.w+b1v.w;

            // K,V: 8 dots (all lanes); q: 2 dots for own head only
            float kv[8];
            #pragma unroll
            for (int f = 0; f < 8; f++) {
                float4 wr = ld4(sw + O_WQKV + l*48 + (4+f)*4);
                kv[f] = fmaf(h0, wr.x, fmaf(h1, wr.y, fmaf(h2, wr.z, h3 * wr.w)));
            }
            float qa, qb;
            {
                float4 wa = ld4(sw + O_WQKV + l*48 + (2*hr)     * 4);
                float4 wb = ld4(sw + O_WQKV + l*48 + (2*hr + 1) * 4);
                qa = fmaf(h0, wa.x, fmaf(h1, wa.y, fmaf(h2, wa.z, h3 * wa.w))) * SC;
                qb = fmaf(h0, wb.x, fmaf(h1, wb.y, fmaf(h2, wb.z, h3 * wb.w))) * SC;
            }

            // publish this state's K/V, head-split layout:
            // [state][head] = (k0, k1, v0, v1); roles 0 and 1 write in parallel
            if (r == 0) {
                *(float4*)(sw + O_SKV + (l*16 + 2*s + 0) * 4) =
                    make_float4(kv[0], kv[1], kv[4], kv[5]);   // head0
            }
            if (r == 1) {
                *(float4*)(sw + O_SKV + (l*16 + 2*s + 1) * 4) =
                    make_float4(kv[2], kv[3], kv[6], kv[7]);   // head1
            }
            __syncwarp();

            // histogram-weighted softmax over 8 states, own head only (8 ex2,
            // one LDS.128 per iter, no selects)
            float den = 0.f, aa = 0.f, ab = 0.f;
            #pragma unroll
            for (int j = 0; j < 8; j++) {
                float4 c4 = ld4(sw + O_SKV + (l*16 + 2*j + hr) * 4);
                float w  = cw[j] * ex2(fmaf(qa, c4.x, qb * c4.y));
                den += w; aa = fmaf(w, c4.z, aa); ab = fmaf(w, c4.w, ab);
            }
            float inv = rcpa(den);
            float oa = aa * inv, ob = ab * inv;

            // recombine heads: partner role is lane^2 (other head, same state)
            float oax = __shfl_xor_sync(0xffffffffu, oa, 2);
            float obx = __shfl_xor_sync(0xffffffffu, ob, 2);
            float o0 = hr ? oax : oa, o1 = hr ? obx : ob;
            float o2 = hr ? oa : oax, o3 = hr ? ob : obx;

            // Wo projection + residual
            float4 wo0 = ld4(sw + O_WO + l*16 + 0);
            float4 wo1 = ld4(sw + O_WO + l*16 + 4);
            float4 wo2 = ld4(sw + O_WO + l*16 + 8);
            float4 wo3 = ld4(sw + O_WO + l*16 + 12);
            float y0 = x0 + o0*wo0.x + o1*wo0.y + o2*wo0.z + o3*wo0.w;
            float y1 = x1 + o0*wo1.x + o1*wo1.y + o2*wo1.z + o3*wo1.w;
            float y2 = x2 + o0*wo2.x + o1*wo2.y + o2*wo2.z + o3*wo2.w;
            float y3 = x3 + o0*wo3.x + o1*wo3.y + o2*wo3.z + o3*wo3.w;

            // LN2
            float4 g2 = ld4(sw + O_LN2G + l*4), b2v = ld4(sw + O_LN2B + l*4);
            mu = 0.25f*(y0+y1+y2+y3);
            d0 = y0-mu; d1 = y1-mu; d2 = y2-mu; d3 = y3-mu;
            rr = rsqa(fmaf(0.25f, d0*d0+d1*d1+d2*d2+d3*d3, 1e-5f));
            h0 = d0*rr*g2.x+b2v.x; h1 = d1*rr*g2.y+b2v.y;
            h2 = d2*rr*g2.z+b2v.z; h3 = d3*rr*g2.w+b2v.w;

            // FFN: role r owns hidden units 4r..4r+3 (4 branch-free gelu/lane)
            float p0 = 0.f, p1 = 0.f, p2 = 0.f, p3 = 0.f;
            #pragma unroll
            for (int j = 0; j < 4; j++) {
                int fl = r * 4 + j;
                float4 w1r = ld4(sw + O_W1 + l*64 + fl*4);
                float  bb  = sw[O_B1 + l*16 + fl];
                float ss = fmaf(h0, w1r.x, fmaf(h1, w1r.y,
                           fmaf(h2, w1r.z, fmaf(h3, w1r.w, bb))));
                float u  = 0.5f * ss * (1.0f + erf_bf(ss * 0.70710678118654752f));
                float4 w2r = ld4(sw + O_W2T + l*64 + fl*4);
                p0 = fmaf(u, w2r.x, p0); p1 = fmaf(u, w2r.y, p1);
                p2 = fmaf(u, w2r.z, p2); p3 = fmaf(u, w2r.w, p3);
            }
            #pragma unroll
            for (int m = 1; m <= 2; m <<= 1) {     // reduce over the 4 roles
                p0 += __shfl_xor_sync(0xffffffffu, p0, m);
                p1 += __shfl_xor_sync(0xffffffffu, p1, m);
                p2 += __shfl_xor_sync(0xffffffffu, p2, m);
                p3 += __shfl_xor_sync(0xffffffffu, p3, m);
            }
            float4 bf2 = ld4(sw + O_B2 + l*4);
            x0 = y0 + bf2.x + p0;
            x1 = y1 + bf2.y + p1;
            x2 = y2 + bf2.z + p2;
            x3 = y3 + bf2.w + p3;
        }

        // logits: role r computes logits 2r, 2r+1 of state s
        float4 owa = ld4(sw + O_OUTW + (2*r)     * 4);
        float4 owb = ld4(sw + O_OUTW + (2*r + 1) * 4);
        float la = fmaf(x0, owa.x, fmaf(x1, owa.y, fmaf(x2, owa.z, x3 * owa.w)));
        float lb = fmaf(x0, owb.x, fmaf(x1, owb.y, fmaf(x2, owb.z, x3 * owb.w)));
        *(float2*)(sw + O_SLOG + s * 8 + 2 * r) = make_float2(la, lb);
    } else {
        my = tp[t];                                // own 4 scatter tokens
    }

    __syncthreads();                               // the ONLY block barrier

    // ---- scatter: 4 contiguous tokens per thread (2x STG.128 each) ----
    float4* op = (float4*)(out + ((size_t)b * NS + 4 * t) * NV);
    const float4* l0 = (const float4*)(sw + O_SLOG + my.x * NV);
    const float4* l1 = (const float4*)(sw + O_SLOG + my.y * NV);
    const float4* l2 = (const float4*)(sw + O_SLOG + my.z * NV);
    const float4* l3 = (const float4*)(sw + O_SLOG + my.w * NV);
    op[0] = l0[0]; op[1] = l0[1];
    op[2] = l1[0]; op[3] = l1[1];
    op[4] = l2[0]; op[5] = l2[1];
    op[6] = l3[0]; op[7] = l3[1];
}

// ---------------------------------------------------------------------------
extern "C" void kernel_launch(void* const* d_in, const int* in_sizes, int n_in,
                              void* d_out, int out_size)
{
    const int*   tok   = (const int*)  d_in[0];
    const float* emb   = (const float*)d_in[1];
    const float* ln1_g = (const float*)d_in[2];
    const float* ln1_b = (const float*)d_in[3];
    const float* wqkv  = (const float*)d_in[4];
    const float* wo    = (const float*)d_in[5];
    const float* ln2_g = (const float*)d_in[6];
    const float* ln2_b = (const float*)d_in[7];
    const float* w1    = (const float*)d_in[8];
    const float* b1    = (const float*)d_in[9];
    const float* w2    = (const float*)d_in[10];
    const float* b2    = (const float*)d_in[11];
    const float* out_w = (const float*)d_in[12];
    float* out = (float*)d_out;

    fused_kernel<<<NB, 256>>>(tok, emb, ln1_g, ln1_b, wqkv, wo,
                              ln2_g, ln2_b, w1, b1, w2, b2, out_w, out);
}